// round 11
// baseline (speedup 1.0000x reference)
#include <cuda_runtime.h>
#include <cstdint>

// CausalConv1d (R11, final): R6 (best: 81.6us, DRAM 77.8%) + evict-first
// (.cs) STREAMING LOADS. R6-R10 established the plateau: occupancy 42-65%,
// L1 46-72%, store policy and wave structure all leave DRAM pinned at ~77%
// (~6.1 TB/s) -> mixed 50/50 read/write HBM turnaround is the ceiling.
// .cs reads keep the zero-reuse 256MB stream from churning the hot 80KB
// weight set out of L2 (the last identifiable source of avoidable DRAM work).
//
// out[b,h] = S0*w[h,0]+S1*w[h,1]+S2*w[h,2]+x*w[h,3]+bias[h]
// new_state[b,h,:] = {state[b,h,1], state[b,h,2], x[b,h]}

#define HIDDEN 4096
#define BATCH  4096
#define PAIRS  ((int64_t)BATCH * HIDDEN)
#define TPB    256
#define PAIRS_PER_BLOCK (TPB * 4)    // 1024 consecutive pairs, single row segment

__device__ __forceinline__ float4 ldcs4(const float* p) {
    return __ldcs(reinterpret_cast<const float4*>(p));
}

__global__ void __launch_bounds__(TPB)
causal_conv1d_kernel(const float* __restrict__ x,
                     const float* __restrict__ state,
                     const float* __restrict__ weight,   // [HIDDEN,4] row-major
                     const float* __restrict__ bias,     // [HIDDEN]
                     float* __restrict__ out,            // [BATCH,HIDDEN]
                     float* __restrict__ new_state)      // [BATCH,HIDDEN,3]
{
    __shared__ float w_s[4][PAIRS_PER_BLOCK];   // SoA: tap k, local h
    __shared__ float b_s[PAIRS_PER_BLOCK];

    const int tid = threadIdx.x;
    const int64_t blk_p0 = (int64_t)blockIdx.x * PAIRS_PER_BLOCK;
    const int hb = (int)(blk_p0 & (HIDDEN - 1));   // block's h base (1024-aligned)

    // ---- cooperative weight load + transpose (coalesced LDG, conflict-free STS) ----
    const float4* wslice = reinterpret_cast<const float4*>(weight + (int64_t)hb * 4);
    #pragma unroll
    for (int i = 0; i < 4; ++i) {
        int r = tid + i * TPB;                 // local h row [0,1024)
        float4 w = wslice[r];                  // lanes stride 16B -> coalesced
        w_s[0][r] = w.x;                       // lanes stride 4B -> conflict-free
        w_s[1][r] = w.y;
        w_s[2][r] = w.z;
        w_s[3][r] = w.w;
    }
    {
        const float4* bslice = reinterpret_cast<const float4*>(bias + hb);
        reinterpret_cast<float4*>(b_s)[tid] = bslice[tid];
    }
    __syncthreads();

    // ---- per-thread: 4 consecutive pairs ----
    const int64_t p0 = blk_p0 + (int64_t)tid * 4;
    const int hl = tid * 4;                    // local h offset

    const float4 t0 = *reinterpret_cast<const float4*>(&w_s[0][hl]);
    const float4 t1 = *reinterpret_cast<const float4*>(&w_s[1][hl]);
    const float4 t2 = *reinterpret_cast<const float4*>(&w_s[2][hl]);
    const float4 t3 = *reinterpret_cast<const float4*>(&w_s[3][hl]);
    const float4 bv = *reinterpret_cast<const float4*>(&b_s[hl]);

    // ---- streaming loads (4x LDG.128.CS: zero-reuse, evict-first) ----
    const float4 xv = ldcs4(x + p0);
    const float*  sb = state + p0 * 3;
    const float4 s0 = ldcs4(sb + 0);   // S0..S3
    const float4 s1 = ldcs4(sb + 4);   // S4..S7
    const float4 s2 = ldcs4(sb + 8);   // S8..S11

    // ---- compute: pair j taps = {S[3j],S[3j+1],S[3j+2],X[j]} ----
    float4 ov;
    ov.x = fmaf(s0.x, t0.x, fmaf(s0.y, t1.x, fmaf(s0.z, t2.x, fmaf(xv.x, t3.x, bv.x))));
    ov.y = fmaf(s0.w, t0.y, fmaf(s1.x, t1.y, fmaf(s1.y, t2.y, fmaf(xv.y, t3.y, bv.y))));
    ov.z = fmaf(s1.z, t0.z, fmaf(s1.w, t1.z, fmaf(s2.x, t2.z, fmaf(xv.z, t3.z, bv.z))));
    ov.w = fmaf(s2.y, t0.w, fmaf(s2.z, t1.w, fmaf(s2.w, t2.w, fmaf(xv.w, t3.w, bv.w))));

    // ---- new_state flat = {S1,S2,X0, S4,S5,X1, S7,S8,X2, S10,S11,X3} ----
    const float4 n0 = make_float4(s0.y, s0.z, xv.x, s1.x);
    const float4 n1 = make_float4(s1.y, xv.y, s1.w, s2.x);
    const float4 n2 = make_float4(xv.z, s2.z, s2.w, xv.w);

    // ---- stores (4x STG.128, coalesced, default policy — R8 showed .cs hurts) ----
    *reinterpret_cast<float4*>(out + p0) = ov;
    float4* np = reinterpret_cast<float4*>(new_state + p0 * 3);
    np[0] = n0;
    np[1] = n1;
    np[2] = n2;
}

extern "C" void kernel_launch(void* const* d_in, const int* in_sizes, int n_in,
                              void* d_out, int out_size)
{
    const float* x      = (const float*)d_in[0];
    const float* state  = (const float*)d_in[1];
    const float* weight = (const float*)d_in[2];
    const float* bias   = (const float*)d_in[3];

    float* out       = (float*)d_out;
    float* new_state = (float*)d_out + PAIRS;

    const int blocks = (int)(PAIRS / PAIRS_PER_BLOCK);   // 16384
    causal_conv1d_kernel<<<blocks, TPB>>>(x, state, weight, bias, out, new_state);
}

// round 12
// speedup vs baseline: 1.1087x; 1.1087x over previous
#include <cuda_runtime.h>
#include <cstdint>

// CausalConv1d (FINAL = R6): weights/bias staged in shared memory.
//
// Converged result after 11 rounds: the decisive fix was removing the
// per-thread weight gather from L1tex (lane stride 64B -> 16 wavefronts/LDG
// made L1 the binding pipe); staging weights in smem (SoA per-tap,
// conflict-free LDS.128) dropped 96.3 -> 81.6us. All further levers
// (occupancy 42-65%, preamble amortization, .cs loads/stores, persistent
// CTAs, MLP 4->8) leave DRAM pinned at ~77% (~6.1 TB/s) with slack
// everywhere else: the mixed 50/50 read/write HBM turnaround ceiling for
// this 512MB streaming pattern.
//
// out[b,h] = S0*w[h,0]+S1*w[h,1]+S2*w[h,2]+x*w[h,3]+bias[h]
// new_state[b,h,:] = {state[b,h,1], state[b,h,2], x[b,h]}

#define HIDDEN 4096
#define BATCH  4096
#define PAIRS  ((int64_t)BATCH * HIDDEN)
#define TPB    256
#define PAIRS_PER_BLOCK (TPB * 4)    // 1024 consecutive pairs, single row segment

__global__ void __launch_bounds__(TPB)
causal_conv1d_kernel(const float* __restrict__ x,
                     const float* __restrict__ state,
                     const float* __restrict__ weight,   // [HIDDEN,4] row-major
                     const float* __restrict__ bias,     // [HIDDEN]
                     float* __restrict__ out,            // [BATCH,HIDDEN]
                     float* __restrict__ new_state)      // [BATCH,HIDDEN,3]
{
    __shared__ float w_s[4][PAIRS_PER_BLOCK];   // SoA: tap k, local h
    __shared__ float b_s[PAIRS_PER_BLOCK];

    const int tid = threadIdx.x;
    const int64_t blk_p0 = (int64_t)blockIdx.x * PAIRS_PER_BLOCK;
    const int hb = (int)(blk_p0 & (HIDDEN - 1));   // block's h base (1024-aligned)

    // ---- cooperative weight load + transpose (coalesced LDG, conflict-free STS) ----
    const float4* wslice = reinterpret_cast<const float4*>(weight + (int64_t)hb * 4);
    #pragma unroll
    for (int i = 0; i < 4; ++i) {
        int r = tid + i * TPB;                 // local h row [0,1024)
        float4 w = wslice[r];                  // lanes stride 16B -> coalesced
        w_s[0][r] = w.x;                       // lanes stride 4B -> conflict-free
        w_s[1][r] = w.y;
        w_s[2][r] = w.z;
        w_s[3][r] = w.w;
    }
    {
        const float4* bslice = reinterpret_cast<const float4*>(bias + hb);
        reinterpret_cast<float4*>(b_s)[tid] = bslice[tid];
    }
    __syncthreads();

    // ---- per-thread: 4 consecutive pairs ----
    const int64_t p0 = blk_p0 + (int64_t)tid * 4;
    const int hl = tid * 4;                    // local h offset

    // tap vectors from smem: lane stride 16B -> conflict-free LDS.128
    const float4 t0 = *reinterpret_cast<const float4*>(&w_s[0][hl]);
    const float4 t1 = *reinterpret_cast<const float4*>(&w_s[1][hl]);
    const float4 t2 = *reinterpret_cast<const float4*>(&w_s[2][hl]);
    const float4 t3 = *reinterpret_cast<const float4*>(&w_s[3][hl]);
    const float4 bv = *reinterpret_cast<const float4*>(&b_s[hl]);

    // ---- streaming loads (4x LDG.128, fully coalesced, default policy) ----
    const float4 xv = *reinterpret_cast<const float4*>(x + p0);
    const float4* sp = reinterpret_cast<const float4*>(state + p0 * 3);
    const float4 s0 = sp[0];   // S0..S3
    const float4 s1 = sp[1];   // S4..S7
    const float4 s2 = sp[2];   // S8..S11

    // ---- compute: pair j taps = {S[3j],S[3j+1],S[3j+2],X[j]} ----
    float4 ov;
    ov.x = fmaf(s0.x, t0.x, fmaf(s0.y, t1.x, fmaf(s0.z, t2.x, fmaf(xv.x, t3.x, bv.x))));
    ov.y = fmaf(s0.w, t0.y, fmaf(s1.x, t1.y, fmaf(s1.y, t2.y, fmaf(xv.y, t3.y, bv.y))));
    ov.z = fmaf(s1.z, t0.z, fmaf(s1.w, t1.z, fmaf(s2.x, t2.z, fmaf(xv.z, t3.z, bv.z))));
    ov.w = fmaf(s2.y, t0.w, fmaf(s2.z, t1.w, fmaf(s2.w, t2.w, fmaf(xv.w, t3.w, bv.w))));

    // ---- new_state flat = {S1,S2,X0, S4,S5,X1, S7,S8,X2, S10,S11,X3} ----
    const float4 n0 = make_float4(s0.y, s0.z, xv.x, s1.x);
    const float4 n1 = make_float4(s1.y, xv.y, s1.w, s2.x);
    const float4 n2 = make_float4(xv.z, s2.z, s2.w, xv.w);

    // ---- stores (4x STG.128, coalesced, default policy) ----
    *reinterpret_cast<float4*>(out + p0) = ov;
    float4* np = reinterpret_cast<float4*>(new_state + p0 * 3);
    np[0] = n0;
    np[1] = n1;
    np[2] = n2;
}

extern "C" void kernel_launch(void* const* d_in, const int* in_sizes, int n_in,
                              void* d_out, int out_size)
{
    const float* x      = (const float*)d_in[0];
    const float* state  = (const float*)d_in[1];
    const float* weight = (const float*)d_in[2];
    const float* bias   = (const float*)d_in[3];

    float* out       = (float*)d_out;
    float* new_state = (float*)d_out + PAIRS;

    const int blocks = (int)(PAIRS / PAIRS_PER_BLOCK);   // 16384
    causal_conv1d_kernel<<<blocks, TPB>>>(x, state, weight, bias, out, new_state);
}